// round 1
// baseline (speedup 1.0000x reference)
#include <cuda_runtime.h>

#define T_STEPS 500
#define N_NEUR  20000
#define DT      0.1f

// param indices (PNAMES order)
// 0 decay_ca, 1 rho_ca, 2 p_tau, 3 p_scale, 4 p_mdp, 5 q_tau, 6 q_scale, 7 q_mdp,
// 8 n_tau, 9 n_scale, 10 n_mdp, 11 f_tau, 12 f_scale, 13 f_mdp, 14 e_tau,
// 15 e_scale, 16 e_mdp, 17 h_alpha, 18 h_scale, 19 h_mdp, 20 C_m, 21 g_Ca,
// 22 g_Ks, 23 g_Kf, 24 g_L, 25 E_Ca, 26 E_K, 27 E_L

__device__ __forceinline__ float sigm(float z) {
    // sigmoid(z) = 1/(1+exp(-z)); accurate path (expf + IEEE div)
    return 1.0f / (1.0f + expf(-z));
}

__global__ void __launch_bounds__(64, 8) hh_kernel(
    const float* __restrict__ i_inj,   // [T, N]
    const float* __restrict__ x0,      // [7, N]
    const float* __restrict__ params,  // [28]
    float* __restrict__ out)           // [T, 7, N]
{
    const int n = blockIdx.x * blockDim.x + threadIdx.x;
    if (n >= N_NEUR) return;

    // ---- load params, precompute per-run constants (once; amortized over 500 steps)
    const float decay_ca = params[0];
    const float rho_ca   = params[1];
    const float p_tau = params[2],  p_kinv = 1.0f / params[3],  p_mdp = params[4];
    const float q_tau = params[5],  q_kinv = 1.0f / params[6],  q_mdp = params[7];
    const float n_tau = params[8],  n_kinv = 1.0f / params[9],  n_mdp = params[10];
    const float f_tau = params[11], f_kinv = 1.0f / params[12], f_mdp = params[13];
    const float e_tau = params[14], e_kinv = 1.0f / params[15], e_mdp = params[16];
    const float h_alpha = params[17], h_kinv = 1.0f / params[18], h_mdp = params[19];
    const float C_m = params[20], g_Ca = params[21], g_Ks = params[22];
    const float g_Kf = params[23], g_L = params[24];
    const float E_Ca = params[25], E_K = params[26], E_L = params[27];

    // gate(x,V) = tau*dt/(tau+dt) * (x/dt + inf/tau) = A*x + B*inf
    const float Ap = p_tau / (p_tau + DT), Bp = DT / (p_tau + DT);
    const float Aq = q_tau / (q_tau + DT), Bq = DT / (q_tau + DT);
    const float An = n_tau / (n_tau + DT), Bn = DT / (n_tau + DT);
    const float Af = f_tau / (f_tau + DT), Bf = DT / (f_tau + DT);
    const float Ae = e_tau / (e_tau + DT), Be = DT / (e_tau + DT);

    const float dt_over_Cm = DT / C_m;
    const float inv_decay  = 1.0f / decay_ca;
    const float rho_dt     = rho_ca * DT;
    const float one_m_a    = 1.0f - h_alpha;

    // ---- initial state [V, p, q, n, e, f, cac]
    float V   = x0[0 * N_NEUR + n];
    float p   = x0[1 * N_NEUR + n];
    float q   = x0[2 * N_NEUR + n];
    float nn  = x0[3 * N_NEUR + n];
    float e   = x0[4 * N_NEUR + n];
    float f   = x0[5 * N_NEUR + n];
    float cac = x0[6 * N_NEUR + n];

    const float* inj = i_inj + n;
    float* o = out + n;

    #pragma unroll 1
    for (int t = 0; t < T_STEPS; ++t) {
        const float icur = __ldcs(inj);
        inj += N_NEUR;

        // h from OLD cac
        const float h = one_m_a + h_alpha * sigm((cac - h_mdp) * h_kinv);

        const float gef  = g_Ca * e * e * f * h;       // shared by i_ca / i_ca2
        const float i_ca = gef * (V - E_Ca);
        const float VmEK = V - E_K;
        const float i_ks = g_Ks * nn * VmEK;
        const float p2   = p * p;
        const float i_kf = g_Kf * p2 * p2 * q * VmEK;
        const float i_l  = g_L * (V - E_L);

        V = V + (icur - i_ca - i_ks - i_kf - i_l) * dt_over_Cm;

        // cac uses I_Ca recomputed with the UPDATED V
        const float i_ca2 = gef * (V - E_Ca);
        cac = cac + (-i_ca2 * rho_dt - cac * inv_decay * DT);

        // gates use UPDATED V (5 independent sigmoid chains -> ILP)
        p  = Ap * p  + Bp * sigm((V - p_mdp) * p_kinv);
        q  = Aq * q  + Bq * sigm((V - q_mdp) * q_kinv);
        e  = Ae * e  + Be * sigm((V - e_mdp) * e_kinv);
        f  = Af * f  + Bf * sigm((V - f_mdp) * f_kinv);
        nn = An * nn + Bn * sigm((V - n_mdp) * n_kinv);

        // store [V, p, q, n, e, f, cac] — streaming (write-once, keep out of L2)
        __stcs(o + 0 * N_NEUR, V);
        __stcs(o + 1 * N_NEUR, p);
        __stcs(o + 2 * N_NEUR, q);
        __stcs(o + 3 * N_NEUR, nn);
        __stcs(o + 4 * N_NEUR, e);
        __stcs(o + 5 * N_NEUR, f);
        __stcs(o + 6 * N_NEUR, cac);
        o += 7 * N_NEUR;
    }
}

extern "C" void kernel_launch(void* const* d_in, const int* in_sizes, int n_in,
                              void* d_out, int out_size) {
    const float* i_inj  = (const float*)d_in[0];
    const float* x0     = (const float*)d_in[1];
    const float* params = (const float*)d_in[2];
    float* out = (float*)d_out;

    const int block = 64;
    const int grid  = (N_NEUR + block - 1) / block;  // 313 blocks -> all 148 SMs populated
    hh_kernel<<<grid, block>>>(i_inj, x0, params, out);
}

// round 2
// speedup vs baseline: 1.3951x; 1.3951x over previous
#include <cuda_runtime.h>

#define T_STEPS 500
#define N_NEUR  20000
#define DT      0.1f
#define LOG2E   1.442695040888963f

// fast sigmoid: sigm(z) = 1/(1+2^(-z*log2e)), ex2.approx + rcp.approx (~2^-22 rel err each)
// caller pre-folds constants so the argument arrives as t = (mdp - V)*kinv*LOG2E
__device__ __forceinline__ float sigm_from_t(float t) {
    float e;
    asm("ex2.approx.f32 %0, %1;" : "=f"(e) : "f"(t));
    float r;
    asm("rcp.approx.f32 %0, %1;" : "=f"(r) : "f"(1.0f + e));
    return r;
}

__global__ void __launch_bounds__(32, 16) hh_kernel(
    const float* __restrict__ i_inj,   // [T, N]
    const float* __restrict__ x0,      // [7, N]
    const float* __restrict__ params,  // [28]
    float* __restrict__ out)           // [T, 7, N]
{
    const int n = blockIdx.x * blockDim.x + threadIdx.x;
    if (n >= N_NEUR) return;

    // ---- params
    const float decay_ca = params[0];
    const float rho_ca   = params[1];
    const float p_tau = params[2],  p_scale = params[3],  p_mdp = params[4];
    const float q_tau = params[5],  q_scale = params[6],  q_mdp = params[7];
    const float n_tau = params[8],  n_scale = params[9],  n_mdp = params[10];
    const float f_tau = params[11], f_scale = params[12], f_mdp = params[13];
    const float e_tau = params[14], e_scale = params[15], e_mdp = params[16];
    const float h_alpha = params[17], h_scale = params[18], h_mdp = params[19];
    const float C_m = params[20], g_Ca = params[21], g_Ks = params[22];
    const float g_Kf = params[23], g_L = params[24];
    const float E_Ca = params[25], E_K = params[26], E_L = params[27];

    // sigmoid argument as single FFMA: t = V*c1 + c0 where
    //   t = (mdp - V)/scale * LOG2E  ->  c1 = -LOG2E/scale, c0 = mdp*LOG2E/scale
    const float p_c1 = -LOG2E / p_scale, p_c0 = p_mdp * LOG2E / p_scale;
    const float q_c1 = -LOG2E / q_scale, q_c0 = q_mdp * LOG2E / q_scale;
    const float n_c1 = -LOG2E / n_scale, n_c0 = n_mdp * LOG2E / n_scale;
    const float f_c1 = -LOG2E / f_scale, f_c0 = f_mdp * LOG2E / f_scale;
    const float e_c1 = -LOG2E / e_scale, e_c0 = e_mdp * LOG2E / e_scale;
    const float h_c1 = -LOG2E / h_scale, h_c0 = h_mdp * LOG2E / h_scale;

    // gate(x,V) = A*x + B*sigm ; A = tau/(tau+dt), B = dt/(tau+dt)
    const float Ap = p_tau / (p_tau + DT), Bp = DT / (p_tau + DT);
    const float Aq = q_tau / (q_tau + DT), Bq = DT / (q_tau + DT);
    const float An = n_tau / (n_tau + DT), Bn = DT / (n_tau + DT);
    const float Af = f_tau / (f_tau + DT), Bf = DT / (f_tau + DT);
    const float Ae = e_tau / (e_tau + DT), Be = DT / (e_tau + DT);

    const float dt_over_Cm = DT / C_m;
    const float cdecay     = 1.0f - DT / decay_ca;   // cac = cac*cdecay - i_ca2*rho_dt
    const float rho_dt     = rho_ca * DT;
    const float one_m_a    = 1.0f - h_alpha;

    // ---- initial state
    float V   = x0[0 * N_NEUR + n];
    float p   = x0[1 * N_NEUR + n];
    float q   = x0[2 * N_NEUR + n];
    float nn  = x0[3 * N_NEUR + n];
    float e   = x0[4 * N_NEUR + n];
    float f   = x0[5 * N_NEUR + n];
    float cac = x0[6 * N_NEUR + n];

    const float* inj = i_inj + n;
    float* o = out + n;

    #pragma unroll 1
    for (int t = 0; t < T_STEPS; ++t) {
        const float icur = __ldcs(inj);
        inj += N_NEUR;

        // h from OLD cac (1 FFMA + EX2 + FADD + RCP + 1 FFMA)
        const float h = fmaf(h_alpha, sigm_from_t(fmaf(cac, h_c1, h_c0)), one_m_a);

        const float gef  = g_Ca * e * e * f * h;     // shared by i_ca / i_ca2
        const float i_ca = gef * (V - E_Ca);
        const float VmEK = V - E_K;
        const float i_ks = g_Ks * nn * VmEK;
        const float p2   = p * p;
        const float i_kf = g_Kf * p2 * p2 * q * VmEK;
        const float i_l  = g_L * (V - E_L);

        V = fmaf(icur - i_ca - i_ks - i_kf - i_l, dt_over_Cm, V);

        // cac uses I_Ca recomputed with the UPDATED V
        const float i_ca2 = gef * (V - E_Ca);
        cac = fmaf(cac, cdecay, -i_ca2 * rho_dt);

        // 5 independent sigmoid chains on UPDATED V -> ILP across MUFU ops
        p  = fmaf(Ap, p,  Bp * sigm_from_t(fmaf(V, p_c1, p_c0)));
        q  = fmaf(Aq, q,  Bq * sigm_from_t(fmaf(V, q_c1, q_c0)));
        e  = fmaf(Ae, e,  Be * sigm_from_t(fmaf(V, e_c1, e_c0)));
        f  = fmaf(Af, f,  Bf * sigm_from_t(fmaf(V, f_c1, f_c0)));
        nn = fmaf(An, nn, Bn * sigm_from_t(fmaf(V, n_c1, n_c0)));

        // streaming stores (write-once)
        __stcs(o + 0 * N_NEUR, V);
        __stcs(o + 1 * N_NEUR, p);
        __stcs(o + 2 * N_NEUR, q);
        __stcs(o + 3 * N_NEUR, nn);
        __stcs(o + 4 * N_NEUR, e);
        __stcs(o + 5 * N_NEUR, f);
        __stcs(o + 6 * N_NEUR, cac);
        o += 7 * N_NEUR;
    }
}

extern "C" void kernel_launch(void* const* d_in, const int* in_sizes, int n_in,
                              void* d_out, int out_size) {
    const float* i_inj  = (const float*)d_in[0];
    const float* x0     = (const float*)d_in[1];
    const float* params = (const float*)d_in[2];
    float* out = (float*)d_out;

    // 20000/32 = 625 blocks of one warp each -> ~1 warp per SMSP chip-wide, balanced
    hh_kernel<<<625, 32>>>(i_inj, x0, params, out);
}

// round 3
// speedup vs baseline: 3.8857x; 2.7852x over previous
#include <cuda_runtime.h>

#define T_STEPS 500
#define N_NEUR  20000
#define DT      0.1f
#define LOG2E   1.442695040888963f
#define UNROLL  10               // 500 = 10 * 50

// fast sigmoid from prefolded arg t = (mdp - V)/scale * LOG2E :
//   sigm = 1/(1 + 2^t)   (EX2 + FADD + RCP, ~2^-22 rel err each)
__device__ __forceinline__ float sigm_from_t(float t) {
    float e;
    asm("ex2.approx.f32 %0, %1;" : "=f"(e) : "f"(t));
    float r;
    asm("rcp.approx.f32 %0, %1;" : "=f"(r) : "f"(1.0f + e));
    return r;
}

__global__ void __launch_bounds__(32, 16) hh_kernel(
    const float* __restrict__ i_inj,   // [T, N]
    const float* __restrict__ x0,      // [7, N]
    const float* __restrict__ params,  // [28]
    float* __restrict__ out)           // [T, 7, N]
{
    const int n = blockIdx.x * blockDim.x + threadIdx.x;
    if (n >= N_NEUR) return;

    // ---- params
    const float decay_ca = params[0];
    const float rho_ca   = params[1];
    const float p_tau = params[2],  p_scale = params[3],  p_mdp = params[4];
    const float q_tau = params[5],  q_scale = params[6],  q_mdp = params[7];
    const float n_tau = params[8],  n_scale = params[9],  n_mdp = params[10];
    const float f_tau = params[11], f_scale = params[12], f_mdp = params[13];
    const float e_tau = params[14], e_scale = params[15], e_mdp = params[16];
    const float h_alpha = params[17], h_scale = params[18], h_mdp = params[19];
    const float C_m = params[20], g_Ca = params[21], g_Ks = params[22];
    const float g_Kf = params[23], g_L = params[24];
    const float E_Ca = params[25], E_K = params[26], E_L = params[27];

    // sigmoid arg as one FFMA: t = V*c1 + c0
    const float p_c1 = -LOG2E / p_scale, p_c0 = p_mdp * LOG2E / p_scale;
    const float q_c1 = -LOG2E / q_scale, q_c0 = q_mdp * LOG2E / q_scale;
    const float n_c1 = -LOG2E / n_scale, n_c0 = n_mdp * LOG2E / n_scale;
    const float f_c1 = -LOG2E / f_scale, f_c0 = f_mdp * LOG2E / f_scale;
    const float e_c1 = -LOG2E / e_scale, e_c0 = e_mdp * LOG2E / e_scale;
    const float h_c1 = -LOG2E / h_scale, h_c0 = h_mdp * LOG2E / h_scale;

    // gate(x,V) = A*x + B*sigm
    const float Ap = p_tau / (p_tau + DT), Bp = DT / (p_tau + DT);
    const float Aq = q_tau / (q_tau + DT), Bq = DT / (q_tau + DT);
    const float An = n_tau / (n_tau + DT), Bn = DT / (n_tau + DT);
    const float Af = f_tau / (f_tau + DT), Bf = DT / (f_tau + DT);
    const float Ae = e_tau / (e_tau + DT), Be = DT / (e_tau + DT);

    const float dt_over_Cm = DT / C_m;
    const float cdecay     = 1.0f - DT / decay_ca;
    const float rho_dt     = rho_ca * DT;
    const float one_m_a    = 1.0f - h_alpha;

    // ---- initial state
    float V   = x0[0 * N_NEUR + n];
    float p   = x0[1 * N_NEUR + n];
    float q   = x0[2 * N_NEUR + n];
    float nn  = x0[3 * N_NEUR + n];
    float e   = x0[4 * N_NEUR + n];
    float f   = x0[5 * N_NEUR + n];
    float cac = x0[6 * N_NEUR + n];

    const float* inj = i_inj + n;
    float* o = out + n;

    // ---- software pipeline: prefetch UNROLL injected currents ahead
    float cur[UNROLL];
    #pragma unroll
    for (int u = 0; u < UNROLL; ++u)
        cur[u] = __ldcs(inj + u * N_NEUR);
    inj += UNROLL * N_NEUR;

    const int NBLK = T_STEPS / UNROLL;   // 50
    #pragma unroll 1
    for (int blk = 0; blk < NBLK; ++blk) {
        // issue next block's loads NOW (MLP=10); consumed only after this
        // block's ~1600 cycles of compute -> DRAM latency fully hidden
        float nxt[UNROLL];
        if (blk < NBLK - 1) {
            #pragma unroll
            for (int u = 0; u < UNROLL; ++u)
                nxt[u] = __ldcs(inj + u * N_NEUR);
            inj += UNROLL * N_NEUR;
        }

        #pragma unroll
        for (int u = 0; u < UNROLL; ++u) {
            const float icur = cur[u];

            // h from OLD cac
            const float h = fmaf(h_alpha, sigm_from_t(fmaf(cac, h_c1, h_c0)), one_m_a);

            const float gef  = g_Ca * e * e * f * h;   // shared by i_ca / i_ca2
            const float i_ca = gef * (V - E_Ca);
            const float VmEK = V - E_K;
            const float i_ks = g_Ks * nn * VmEK;
            const float p2   = p * p;
            const float i_kf = g_Kf * p2 * p2 * q * VmEK;
            const float i_l  = g_L * (V - E_L);

            // tree-reduced sum to shorten the V chain
            const float itot = icur - ((i_ca + i_ks) + (i_kf + i_l));
            V = fmaf(itot, dt_over_Cm, V);

            // cac uses I_Ca recomputed with UPDATED V
            const float i_ca2 = gef * (V - E_Ca);
            cac = fmaf(cac, cdecay, -i_ca2 * rho_dt);

            // 5 independent sigmoid chains on UPDATED V
            p  = fmaf(Ap, p,  Bp * sigm_from_t(fmaf(V, p_c1, p_c0)));
            q  = fmaf(Aq, q,  Bq * sigm_from_t(fmaf(V, q_c1, q_c0)));
            e  = fmaf(Ae, e,  Be * sigm_from_t(fmaf(V, e_c1, e_c0)));
            f  = fmaf(Af, f,  Bf * sigm_from_t(fmaf(V, f_c1, f_c0)));
            nn = fmaf(An, nn, Bn * sigm_from_t(fmaf(V, n_c1, n_c0)));

            // streaming stores (write-once)
            __stcs(o + 0 * N_NEUR, V);
            __stcs(o + 1 * N_NEUR, p);
            __stcs(o + 2 * N_NEUR, q);
            __stcs(o + 3 * N_NEUR, nn);
            __stcs(o + 4 * N_NEUR, e);
            __stcs(o + 5 * N_NEUR, f);
            __stcs(o + 6 * N_NEUR, cac);
            o += 7 * N_NEUR;
        }

        #pragma unroll
        for (int u = 0; u < UNROLL; ++u)
            cur[u] = nxt[u];
    }
}

extern "C" void kernel_launch(void* const* d_in, const int* in_sizes, int n_in,
                              void* d_out, int out_size) {
    const float* i_inj  = (const float*)d_in[0];
    const float* x0     = (const float*)d_in[1];
    const float* params = (const float*)d_in[2];
    float* out = (float*)d_out;

    // 625 one-warp blocks -> ~1 warp per SMSP chip-wide
    hh_kernel<<<625, 32>>>(i_inj, x0, params, out);
}

// round 4
// speedup vs baseline: 4.4785x; 1.1525x over previous
#include <cuda_runtime.h>

#define T_STEPS 500
#define N_NEUR  20000
#define DT      0.1f
#define UNROLL  10               // 500 = 10 * 50

// sigmoid via single-MUFU tanh: sigma(z) = 0.5*tanh(z/2) + 0.5
// caller prefolds so the argument arrives as t = (V - mdp)/(2*scale)
__device__ __forceinline__ float fast_tanh(float t) {
    float r;
    asm("tanh.approx.f32 %0, %1;" : "=f"(r) : "f"(t));
    return r;
}

__global__ void __launch_bounds__(32, 16) hh_kernel(
    const float* __restrict__ i_inj,   // [T, N]
    const float* __restrict__ x0,      // [7, N]
    const float* __restrict__ params,  // [28]
    float* __restrict__ out)           // [T, 7, N]
{
    const int n = blockIdx.x * blockDim.x + threadIdx.x;
    if (n >= N_NEUR) return;

    // ---- params
    const float decay_ca = params[0];
    const float rho_ca   = params[1];
    const float p_tau = params[2],  p_scale = params[3],  p_mdp = params[4];
    const float q_tau = params[5],  q_scale = params[6],  q_mdp = params[7];
    const float n_tau = params[8],  n_scale = params[9],  n_mdp = params[10];
    const float f_tau = params[11], f_scale = params[12], f_mdp = params[13];
    const float e_tau = params[14], e_scale = params[15], e_mdp = params[16];
    const float h_alpha = params[17], h_scale = params[18], h_mdp = params[19];
    const float C_m = params[20], g_Ca = params[21], g_Ks = params[22];
    const float g_Kf = params[23], g_L = params[24];
    const float E_Ca = params[25], E_K = params[26], E_L = params[27];

    // tanh argument as one FFMA: t = V*c1 + c0, with c1 = 1/(2*scale), c0 = -mdp/(2*scale)
    const float p_c1 = 0.5f / p_scale, p_c0 = -p_mdp * 0.5f / p_scale;
    const float q_c1 = 0.5f / q_scale, q_c0 = -q_mdp * 0.5f / q_scale;
    const float n_c1 = 0.5f / n_scale, n_c0 = -n_mdp * 0.5f / n_scale;
    const float f_c1 = 0.5f / f_scale, f_c0 = -f_mdp * 0.5f / f_scale;
    const float e_c1 = 0.5f / e_scale, e_c0 = -e_mdp * 0.5f / e_scale;
    const float h_c1 = 0.5f / h_scale, h_c0 = -h_mdp * 0.5f / h_scale;

    // gate(x,V) = A*x + B*sigma = (A*x + B/2) + (B/2)*tanh  -> 2 FFMA + 1 MUFU
    const float Ap = p_tau / (p_tau + DT), Bp = 0.5f * DT / (p_tau + DT);
    const float Aq = q_tau / (q_tau + DT), Bq = 0.5f * DT / (q_tau + DT);
    const float An = n_tau / (n_tau + DT), Bn = 0.5f * DT / (n_tau + DT);
    const float Af = f_tau / (f_tau + DT), Bf = 0.5f * DT / (f_tau + DT);
    const float Ae = e_tau / (e_tau + DT), Be = 0.5f * DT / (e_tau + DT);

    // h = 1 + (sigma-1)*alpha = (1 - alpha/2) + (alpha/2)*tanh
    const float h_b = 0.5f * h_alpha;
    const float h_a = 1.0f - h_b;

    const float dt_over_Cm = DT / C_m;
    const float cdecay     = 1.0f - DT / decay_ca;
    const float rho_dt     = rho_ca * DT;

    // ---- initial state
    float V   = x0[0 * N_NEUR + n];
    float p   = x0[1 * N_NEUR + n];
    float q   = x0[2 * N_NEUR + n];
    float nn  = x0[3 * N_NEUR + n];
    float e   = x0[4 * N_NEUR + n];
    float f   = x0[5 * N_NEUR + n];
    float cac = x0[6 * N_NEUR + n];

    const float* inj = i_inj + n;
    float* o = out + n;

    // ---- software pipeline: prefetch UNROLL injected currents ahead (MLP=10)
    float cur[UNROLL];
    #pragma unroll
    for (int u = 0; u < UNROLL; ++u)
        cur[u] = __ldcs(inj + u * N_NEUR);
    inj += UNROLL * N_NEUR;

    const int NBLK = T_STEPS / UNROLL;   // 50
    #pragma unroll 1
    for (int blk = 0; blk < NBLK; ++blk) {
        float nxt[UNROLL];
        if (blk < NBLK - 1) {
            #pragma unroll
            for (int u = 0; u < UNROLL; ++u)
                nxt[u] = __ldcs(inj + u * N_NEUR);
            inj += UNROLL * N_NEUR;
        }

        #pragma unroll
        for (int u = 0; u < UNROLL; ++u) {
            const float icur = cur[u];

            // h from OLD cac: FFMA -> TANH -> FFMA
            const float h = fmaf(h_b, fast_tanh(fmaf(cac, h_c1, h_c0)), h_a);

            const float gef  = g_Ca * e * e * f * h;   // shared by i_ca / i_ca2
            const float i_ca = gef * (V - E_Ca);
            const float VmEK = V - E_K;
            const float i_ks = g_Ks * nn * VmEK;
            const float p2   = p * p;
            const float i_kf = g_Kf * p2 * p2 * q * VmEK;
            const float i_l  = g_L * (V - E_L);

            const float itot = icur - ((i_ca + i_ks) + (i_kf + i_l));
            V = fmaf(itot, dt_over_Cm, V);

            // cac uses I_Ca recomputed with UPDATED V
            const float i_ca2 = gef * (V - E_Ca);
            cac = fmaf(cac, cdecay, -i_ca2 * rho_dt);

            // 5 independent gate chains on UPDATED V: FFMA -> TANH -> FFMA each
            p  = fmaf(Bp, fast_tanh(fmaf(V, p_c1, p_c0)), fmaf(Ap, p,  Bp));
            q  = fmaf(Bq, fast_tanh(fmaf(V, q_c1, q_c0)), fmaf(Aq, q,  Bq));
            e  = fmaf(Be, fast_tanh(fmaf(V, e_c1, e_c0)), fmaf(Ae, e,  Be));
            f  = fmaf(Bf, fast_tanh(fmaf(V, f_c1, f_c0)), fmaf(Af, f,  Bf));
            nn = fmaf(Bn, fast_tanh(fmaf(V, n_c1, n_c0)), fmaf(An, nn, Bn));

            // streaming stores (write-once)
            __stcs(o + 0 * N_NEUR, V);
            __stcs(o + 1 * N_NEUR, p);
            __stcs(o + 2 * N_NEUR, q);
            __stcs(o + 3 * N_NEUR, nn);
            __stcs(o + 4 * N_NEUR, e);
            __stcs(o + 5 * N_NEUR, f);
            __stcs(o + 6 * N_NEUR, cac);
            o += 7 * N_NEUR;
        }

        #pragma unroll
        for (int u = 0; u < UNROLL; ++u)
            cur[u] = nxt[u];
    }
}

extern "C" void kernel_launch(void* const* d_in, const int* in_sizes, int n_in,
                              void* d_out, int out_size) {
    const float* i_inj  = (const float*)d_in[0];
    const float* x0     = (const float*)d_in[1];
    const float* params = (const float*)d_in[2];
    float* out = (float*)d_out;

    // 625 one-warp blocks -> ~1 warp per SMSP chip-wide
    hh_kernel<<<625, 32>>>(i_inj, x0, params, out);
}

// round 5
// speedup vs baseline: 4.4975x; 1.0043x over previous
#include <cuda_runtime.h>

#define T_STEPS 500
#define N_NEUR  20000
#define DT      0.1f
#define UNROLL  10               // 500 = 10 * 50
#define NBLK    (T_STEPS / UNROLL)

// sigmoid via single-MUFU tanh: sigma(z) = 0.5*tanh(z/2) + 0.5
__device__ __forceinline__ float fast_tanh(float t) {
    float r;
    asm("tanh.approx.f32 %0, %1;" : "=f"(r) : "f"(t));
    return r;
}

// ring[phase][step][var][lane]
__global__ void __launch_bounds__(64, 8) hh_kernel(
    const float* __restrict__ i_inj,   // [T, N]
    const float* __restrict__ x0,      // [7, N]
    const float* __restrict__ params,  // [28]
    float* __restrict__ out)           // [T, 7, N]
{
    __shared__ float ring[2][UNROLL][7][32];

    const int lane = threadIdx.x & 31;
    const int wid  = threadIdx.x >> 5;
    const int n    = blockIdx.x * 32 + lane;   // neuron owned by this lane (both warps)

    if (wid == 0) {
        // ======================= PRODUCER WARP =======================
        const float decay_ca = params[0];
        const float rho_ca   = params[1];
        const float p_tau = params[2],  p_scale = params[3],  p_mdp = params[4];
        const float q_tau = params[5],  q_scale = params[6],  q_mdp = params[7];
        const float n_tau = params[8],  n_scale = params[9],  n_mdp = params[10];
        const float f_tau = params[11], f_scale = params[12], f_mdp = params[13];
        const float e_tau = params[14], e_scale = params[15], e_mdp = params[16];
        const float h_alpha = params[17], h_scale = params[18], h_mdp = params[19];
        const float C_m = params[20], g_Ca = params[21], g_Ks = params[22];
        const float g_Kf = params[23], g_L = params[24];
        const float E_Ca = params[25], E_K = params[26], E_L = params[27];

        // tanh arg as one FFMA: t = x*c1 + c0  (c1 = 1/(2*scale), c0 = -mdp/(2*scale))
        const float p_c1 = 0.5f / p_scale, p_c0 = -p_mdp * 0.5f / p_scale;
        const float q_c1 = 0.5f / q_scale, q_c0 = -q_mdp * 0.5f / q_scale;
        const float n_c1 = 0.5f / n_scale, n_c0 = -n_mdp * 0.5f / n_scale;
        const float f_c1 = 0.5f / f_scale, f_c0 = -f_mdp * 0.5f / f_scale;
        const float e_c1 = 0.5f / e_scale, e_c0 = -e_mdp * 0.5f / e_scale;
        const float h_c1 = 0.5f / h_scale, h_c0 = -h_mdp * 0.5f / h_scale;

        // gate(x,V) = (A*x + B/2) + (B/2)*tanh
        const float Ap = p_tau / (p_tau + DT), Bp = 0.5f * DT / (p_tau + DT);
        const float Aq = q_tau / (q_tau + DT), Bq = 0.5f * DT / (q_tau + DT);
        const float An = n_tau / (n_tau + DT), Bn = 0.5f * DT / (n_tau + DT);
        const float Af = f_tau / (f_tau + DT), Bf = 0.5f * DT / (f_tau + DT);
        const float Ae = e_tau / (e_tau + DT), Be = 0.5f * DT / (e_tau + DT);

        const float h_b = 0.5f * h_alpha;
        const float h_a = 1.0f - h_b;
        const float dt_over_Cm = DT / C_m;
        const float cdecay     = 1.0f - DT / decay_ca;
        const float rho_dt     = rho_ca * DT;

        float V   = x0[0 * N_NEUR + n];
        float p   = x0[1 * N_NEUR + n];
        float q   = x0[2 * N_NEUR + n];
        float nn  = x0[3 * N_NEUR + n];
        float e   = x0[4 * N_NEUR + n];
        float f   = x0[5 * N_NEUR + n];
        float cac = x0[6 * N_NEUR + n];

        const float* inj = i_inj + n;

        // prefetch first UNROLL currents (MLP=10)
        float cur[UNROLL];
        #pragma unroll
        for (int u = 0; u < UNROLL; ++u)
            cur[u] = __ldcs(inj + u * N_NEUR);
        inj += UNROLL * N_NEUR;

        #pragma unroll 1
        for (int blk = 0; blk < NBLK; ++blk) {
            float (*buf)[7][32] = ring[blk & 1];

            float nxt[UNROLL];
            if (blk < NBLK - 1) {
                #pragma unroll
                for (int u = 0; u < UNROLL; ++u)
                    nxt[u] = __ldcs(inj + u * N_NEUR);
                inj += UNROLL * N_NEUR;
            }

            #pragma unroll
            for (int u = 0; u < UNROLL; ++u) {
                const float icur = cur[u];

                // h from OLD cac
                const float h = fmaf(h_b, fast_tanh(fmaf(cac, h_c1, h_c0)), h_a);

                const float gef  = g_Ca * e * e * f * h;
                const float i_ca = gef * (V - E_Ca);
                const float VmEK = V - E_K;
                const float i_ks = g_Ks * nn * VmEK;
                const float p2   = p * p;
                const float i_kf = g_Kf * p2 * p2 * q * VmEK;
                const float i_l  = g_L * (V - E_L);

                const float itot = icur - ((i_ca + i_ks) + (i_kf + i_l));
                const float dV   = itot * dt_over_Cm;
                V += dV;

                // i_ca2 = gef*(V_new - E_Ca) = i_ca + gef*dV  (identity, 1 FFMA)
                const float i_ca2 = fmaf(gef, dV, i_ca);
                cac = fmaf(cac, cdecay, -i_ca2 * rho_dt);

                // 5 independent gate chains on UPDATED V
                p  = fmaf(Bp, fast_tanh(fmaf(V, p_c1, p_c0)), fmaf(Ap, p,  Bp));
                q  = fmaf(Bq, fast_tanh(fmaf(V, q_c1, q_c0)), fmaf(Aq, q,  Bq));
                e  = fmaf(Be, fast_tanh(fmaf(V, e_c1, e_c0)), fmaf(Ae, e,  Be));
                f  = fmaf(Bf, fast_tanh(fmaf(V, f_c1, f_c0)), fmaf(Af, f,  Bf));
                nn = fmaf(Bn, fast_tanh(fmaf(V, n_c1, n_c0)), fmaf(An, nn, Bn));

                // stage into SMEM ring (STS, cheap issue; conflict-free)
                buf[u][0][lane] = V;
                buf[u][1][lane] = p;
                buf[u][2][lane] = q;
                buf[u][3][lane] = nn;
                buf[u][4][lane] = e;
                buf[u][5][lane] = f;
                buf[u][6][lane] = cac;
            }

            #pragma unroll
            for (int u = 0; u < UNROLL; ++u)
                cur[u] = nxt[u];

            __syncthreads();   // publish phase blk&1; consumer may now read it
        }
    } else {
        // ======================= CONSUMER WARP =======================
        #pragma unroll 1
        for (int blk = 0; blk < NBLK; ++blk) {
            if (blk > 0) {
                const float (*buf)[7][32] = ring[(blk - 1) & 1];
                float* op = out + (size_t)(blk - 1) * UNROLL * 7 * N_NEUR + n;
                #pragma unroll
                for (int u = 0; u < UNROLL; ++u) {
                    #pragma unroll
                    for (int v = 0; v < 7; ++v)
                        __stcs(op + v * N_NEUR, buf[u][v][lane]);
                    op += 7 * N_NEUR;
                }
            }
            __syncthreads();
        }
    }

    // final drain: phase (NBLK-1)&1 holds steps [490..499]
    __syncthreads();
    if (wid == 1) {
        const float (*buf)[7][32] = ring[(NBLK - 1) & 1];
        float* op = out + (size_t)(NBLK - 1) * UNROLL * 7 * N_NEUR + n;
        #pragma unroll
        for (int u = 0; u < UNROLL; ++u) {
            #pragma unroll
            for (int v = 0; v < 7; ++v)
                __stcs(op + v * N_NEUR, buf[u][v][lane]);
            op += 7 * N_NEUR;
        }
    }
}

extern "C" void kernel_launch(void* const* d_in, const int* in_sizes, int n_in,
                              void* d_out, int out_size) {
    const float* i_inj  = (const float*)d_in[0];
    const float* x0     = (const float*)d_in[1];
    const float* params = (const float*)d_in[2];
    float* out = (float*)d_out;

    // 625 blocks x 64 threads: warp0 = compute, warp1 = store drain
    // -> 1250 resident warps = ~2.1 per SMSP (vs 1.06 before)
    hh_kernel<<<625, 64>>>(i_inj, x0, params, out);
}